// round 16
// baseline (speedup 1.0000x reference)
#include <cuda_runtime.h>
#include <cuda_fp16.h>
#include <cstdint>
#include <cstddef>

#define DIMC 192
#define ROWSTRIDE 576
#define NB   8
#define NTOK 4096
#define BR   128
#define BC   64
#define NTILES (NTOK / BC)
#define NTHREADS 256
#define CS 0.10411755f            /* (192^-0.5) * log2(e) : folded into packed Q/K */

#define LDH   112      /* K fp16x2 row stride (u32); slot(p) = (p&3)*28 + (p>>2) */
#define LDQP  208      /* Q row-pair stride (u32); uint4 = complete HMMA A fragment */
#define LDVP  388      /* V row stride (u32, padded); uint4 = B pairs for 2 MMAs */
#define VTILE 6208     /* 16 * LDVP */

// ---- smem layout (u32 units) ----
#define QH_OFF  0
#define QH_SZ   (8 * 8 * LDQP)      /* 13312 */
#define KH_OFF  (QH_OFF + QH_SZ)
#define KH_SZ   (BC * LDH)          /* 7168 x2 */
#define VB_OFF  (KH_OFF + 2 * KH_SZ)
#define VB_SZ   VTILE               /* 6208 x2 */
#define P_OFF   (VB_OFF + 2 * VB_SZ)   /* 4 rb x 2 mg x 4 kg x 32 lanes x uint4 = 4096 */
#define K2_OFF  (P_OFF + 4096)         /* 2 x 64 */
#define Q2_OFF  (K2_OFF + 128)         /* 128 */
#define SL_OFF  (Q2_OFF + 128)         /* 256 */
#define SMEM_U32 (SL_OFF + 256)
#define SMEM_BYTES (SMEM_U32 * 4)      /* 178,688 B */

// ---- device scratch (converted operands; written by prepass) ----
__device__ uint32_t g_khalf[(size_t)NB * NTOK * LDH];
__device__ uint32_t g_vhalf[(size_t)NB * NTILES * VTILE];
__device__ float    g_k2[NB * NTOK];

__device__ __forceinline__ float sqrt_approx(float x) {
    float r; asm("sqrt.approx.f32 %0, %1;" : "=f"(r) : "f"(x)); return r;
}
__device__ __forceinline__ uint32_t pack_f16(float lo, float hi) {
    uint32_t d;
    asm("cvt.rn.f16x2.f32 %0, %1, %2;" : "=r"(d) : "f"(hi), "f"(lo));
    return d;
}
__device__ __forceinline__ uint32_t h2ex2(uint32_t a) {
    uint32_t d; asm("ex2.approx.f16x2 %0, %1;" : "=r"(d) : "r"(a)); return d;
}
__device__ __forceinline__ uint32_t hadd2u(uint32_t a, uint32_t b) {
    uint32_t d; asm("add.rn.f16x2 %0, %1, %2;" : "=r"(d) : "r"(a), "r"(b)); return d;
}
__device__ __forceinline__ uint32_t pack2q(float lo, float hi, float& sq) {
    uint32_t u = pack_f16(lo, hi);
    __half2 h = *reinterpret_cast<__half2*>(&u);
    float2 f = __half22float2(h);
    sq += f.x * f.x + f.y * f.y;
    return u;
}
__device__ __forceinline__ uint32_t smem_u32p(const void* p) {
    uint32_t a;
    asm("{ .reg .u64 t; cvta.to.shared.u64 t, %1; cvt.u32.u64 %0, t; }" : "=r"(a) : "l"(p));
    return a;
}

#define CP_ASYNC16(dst, src) \
    asm volatile("cp.async.cg.shared.global [%0], [%1], 16;" :: "r"(dst), "l"(src) : "memory")
#define CP_COMMIT() asm volatile("cp.async.commit_group;" ::: "memory")
#define CP_WAIT0()  asm volatile("cp.async.wait_group 0;" ::: "memory")

__device__ __forceinline__ void mma16_f16(float* c,
        uint32_t a0, uint32_t a1, uint32_t a2, uint32_t a3,
        uint32_t b0, uint32_t b1) {
    asm volatile("mma.sync.aligned.m16n8k16.row.col.f32.f16.f16.f32 "
        "{%0,%1,%2,%3}, {%4,%5,%6,%7}, {%8,%9}, {%0,%1,%2,%3};"
        : "+f"(c[0]), "+f"(c[1]), "+f"(c[2]), "+f"(c[3])
        : "r"(a0), "r"(a1), "r"(a2), "r"(a3), "r"(b0), "r"(b1));
}

// ============ prepass (unchanged from R15) ============
__global__ void __launch_bounds__(256)
prepass_kernel(const float* __restrict__ qkv)
{
    __shared__ float Vs[64 * 192];
    const int b   = blockIdx.y;
    const int st  = blockIdx.x;
    const int t0  = st * 64;
    const int tid = threadIdx.x;

    #pragma unroll
    for (int i = 0; i < 12; i++) {
        int idx = tid + i * 256;
        int r = idx / 48, c = (idx - r * 48) * 4;
        *(float4*)(Vs + r * 192 + c) =
            *(const float4*)(qkv + ((size_t)(b * NTOK + t0 + r)) * ROWSTRIDE + 2 * DIMC + c);
    }
    {
        int r = tid >> 2, q4 = tid & 3;
        int t = t0 + r;
        const float* krow = qkv + ((size_t)(b * NTOK + t)) * ROWSTRIDE + DIMC + q4 * 48;
        uint32_t* kdst = g_khalf + ((size_t)(b * NTOK + t)) * LDH;
        float s = 0.f;
        #pragma unroll
        for (int i = 0; i < 12; i++) {
            float4 v = *(const float4*)(krow + i * 4);
            int p0 = q4 * 24 + 2 * i, p1 = p0 + 1;
            kdst[(p0 & 3) * 28 + (p0 >> 2)] = pack2q(v.x * CS, v.y * CS, s);
            kdst[(p1 & 3) * 28 + (p1 >> 2)] = pack2q(v.z * CS, v.w * CS, s);
        }
        s += __shfl_xor_sync(0xffffffffu, s, 1);
        s += __shfl_xor_sync(0xffffffffu, s, 2);
        if (q4 == 0) g_k2[b * NTOK + t] = s;
    }
    __syncthreads();

    uint32_t* vout = g_vhalf + ((size_t)(b * NTILES + st)) * VTILE;
    #pragma unroll
    for (int i = 0; i < 7; i++) {
        int c = tid + i * 256;
        if (i == 6 && c >= 1552) break;
        int rr = c / 97, k4 = c - rr * 97;
        uint4 w = make_uint4(0u, 0u, 0u, 0u);
        if (k4 < 96) {
            int t = rr >> 2, t4 = rr & 3;
            uint32_t vals[4];
            #pragma unroll
            for (int jj = 0; jj < 4; jj++) {
                int k = k4 * 4 + jj;
                int gg = k / 48;
                int rem = k - gg * 48;
                int m = rem >> 1, h = rem & 1;
                int col = 8 * m + gg;
                int key = 16 * t + 8 * h + 2 * t4;
                vals[jj] = pack_f16(Vs[key * 192 + col], Vs[(key + 1) * 192 + col]);
            }
            w = make_uint4(vals[0], vals[1], vals[2], vals[3]);
        }
        *(uint4*)(vout + (size_t)rr * LDVP + k4 * 4) = w;
    }
}

// prefetch converted K/V/k2 (unchanged from R15)
__device__ __forceinline__ void prefetch_tile(uint32_t smb, int b, int st) {
    const int tid = threadIdx.x;
    const int buf = st & 1;
    const uint32_t* ksrc = g_khalf + ((size_t)(b * NTOK + st * BC)) * LDH;
    const uint32_t  kdst = smb + (KH_OFF + buf * KH_SZ) * 4;
    #pragma unroll
    for (int i = 0; i < 7; i++) {
        int cid = (tid + i * NTHREADS) * 4;
        CP_ASYNC16(kdst + (uint32_t)cid * 4, ksrc + cid);
    }
    const uint32_t* vsrc = g_vhalf + ((size_t)(b * NTILES + st)) * VTILE;
    const uint32_t  vdst = smb + (VB_OFF + buf * VB_SZ) * 4;
    #pragma unroll
    for (int i = 0; i < 6; i++) {
        int cid = (tid + i * NTHREADS) * 4;
        CP_ASYNC16(vdst + (uint32_t)cid * 4, vsrc + cid);
    }
    if (tid < 16) {
        int cid = (1536 + tid) * 4;
        CP_ASYNC16(vdst + (uint32_t)cid * 4, vsrc + cid);
    }
    if (tid < 16) {
        CP_ASYNC16(smb + (K2_OFF + buf * 64 + tid * 4) * 4,
                   g_k2 + b * NTOK + st * BC + tid * 4);
    }
}

__global__ void __launch_bounds__(NTHREADS, 1)
qkv_l2attn_kernel(const float* __restrict__ qkv, float* __restrict__ out)
{
    extern __shared__ uint32_t smu[];
    uint32_t* sQH = smu + QH_OFF;
    uint32_t* sKH = smu + KH_OFF;
    uint32_t* sVB = smu + VB_OFF;
    uint32_t* sP  = smu + P_OFF;
    float*    sK2 = (float*)(smu + K2_OFF);
    float*    sQ2 = (float*)(smu + Q2_OFF);
    float*    sL  = (float*)(smu + SL_OFF);
    const uint32_t smb = smem_u32p(smu);

    const int tid  = threadIdx.x;
    const int warp = tid >> 5;
    const int lane = tid & 31;
    const int g    = lane >> 2;
    const int t4   = lane & 3;
    const int rb   = warp >> 1;    // row-block: rows rb*32 .. +32
    const int h    = warp & 1;     // key half (QK) / col half (PV)

    const int b  = blockIdx.y;
    const int q0 = blockIdx.x * BR;

    // ---- prologue: prefetch tile 0; pack Q (A-fragment-native) + q2 (R15-verified) ----
    prefetch_tile(smb, b, 0);
    CP_COMMIT();
    {
        int wb = tid >> 5, rp = (tid >> 2) & 7, q = tid & 3;
        const float* qrow0 = qkv + ((size_t)(b * NTOK + q0 + wb * 16 + rp)) * ROWSTRIDE;
        const float* qrow1 = qrow0 + (size_t)8 * ROWSTRIDE;
        uint32_t* qdst = sQH + wb * (8 * LDQP) + rp * LDQP;
        float slo = 0.f, shi = 0.f;
        #pragma unroll
        for (int si = 0; si < 48; si++) {
            int s = q * 48 + si;
            int kb = s >> 4, r16 = s & 15, t4s = r16 >> 2, j = r16 & 3;
            int p = kb * 8 + t4s + ((j >> 1) << 2);
            const float* src = ((j & 1) ? qrow1 : qrow0) + 2 * p;
            float2 v = *(const float2*)src;
            if (j & 1) qdst[s] = pack2q(v.x * CS, v.y * CS, shi);
            else       qdst[s] = pack2q(v.x * CS, v.y * CS, slo);
        }
        slo += __shfl_xor_sync(0xffffffffu, slo, 1);
        slo += __shfl_xor_sync(0xffffffffu, slo, 2);
        shi += __shfl_xor_sync(0xffffffffu, shi, 1);
        shi += __shfl_xor_sync(0xffffffffu, shi, 2);
        if (q == 0) {
            sQ2[wb * 16 + rp]     = slo;
            sQ2[wb * 16 + rp + 8] = shi;
        }
    }
    __syncthreads();

    float q2a[2], q2b[2];
    #pragma unroll
    for (int mg = 0; mg < 2; mg++) {
        q2a[mg] = sQ2[rb * 32 + mg * 16 + g];
        q2b[mg] = sQ2[rb * 32 + mg * 16 + g + 8];
    }

    float l0[2] = {0.f, 0.f}, l1[2] = {0.f, 0.f};
    float o[24][4];   // [mg*12 + ntl][4]
    #pragma unroll
    for (int n = 0; n < 24; n++) { o[n][0]=0.f; o[n][1]=0.f; o[n][2]=0.f; o[n][3]=0.f; }

    const uint32_t* qPtr0 = sQH + (2 * rb)     * (8 * LDQP) + g * LDQP;
    const uint32_t* qPtr1 = sQH + (2 * rb + 1) * (8 * LDQP) + g * LDQP;
    const uint32_t* kPtrB = sKH + h * (32 * LDH) + g * LDH + t4 * 28;
    uint32_t* pMine = sP + (((rb * 2) * 4) * 32 + lane) * 4;   // + (mg*4 + kg)*128

    for (int st = 0; st < NTILES; ++st) {
        const int buf = st & 1;
        CP_WAIT0();
        __syncthreads();               // bar A: tile st data visible; all prior readers done

        if (st + 1 < NTILES) { prefetch_tile(smb, b, st + 1); CP_COMMIT(); }

        // ---- S = Q K^T (per warp: 32 rows x 32 keys); K fragments reused x4 ----
        const uint32_t* kPtr = kPtrB + buf * KH_SZ;
        float sacc[2][4][4];
        #pragma unroll
        for (int mg = 0; mg < 2; mg++)
            #pragma unroll
            for (int n = 0; n < 4; n++) {
                sacc[mg][n][0]=0.f; sacc[mg][n][1]=0.f;
                sacc[mg][n][2]=0.f; sacc[mg][n][3]=0.f;
            }

        #pragma unroll
        for (int i = 0; i < 6; i++) {
            uint4 qa0 = *(const uint4*)(qPtr0 + (2 * i) * 16 + 4 * t4);
            uint4 qb0 = *(const uint4*)(qPtr0 + (2 * i + 1) * 16 + 4 * t4);
            uint4 qa1 = *(const uint4*)(qPtr1 + (2 * i) * 16 + 4 * t4);
            uint4 qb1 = *(const uint4*)(qPtr1 + (2 * i + 1) * 16 + 4 * t4);
            #pragma unroll
            for (int n = 0; n < 4; n++) {
                uint4 kb = *(const uint4*)(kPtr + n * (8 * LDH) + 4 * i);
                mma16_f16(sacc[0][n], qa0.x, qa0.y, qa0.z, qa0.w, kb.x, kb.y);
                mma16_f16(sacc[0][n], qb0.x, qb0.y, qb0.z, qb0.w, kb.z, kb.w);
                mma16_f16(sacc[1][n], qa1.x, qa1.y, qa1.z, qa1.w, kb.x, kb.y);
                mma16_f16(sacc[1][n], qb1.x, qb1.y, qb1.z, qb1.w, kb.z, kb.w);
            }
        }

        // ---- softmax on own 32 keys; store P A-fragments (k16-group kg = 2h+t) ----
        const float* k2b = sK2 + buf * 64;
        #pragma unroll
        for (int t = 0; t < 2; t++) {
            float sa[2][2][4];
            #pragma unroll
            for (int u = 0; u < 2; u++) {
                const int nl = 2 * t + u;
                float2 k2v = *(const float2*)(k2b + (4 * h + nl) * 8 + 2 * t4);
                #pragma unroll
                for (int mg = 0; mg < 2; mg++) {
                    float d0 = fmaxf(fmaf(sacc[mg][nl][0], -2.f, q2a[mg] + k2v.x), 0.f);
                    float d1 = fmaxf(fmaf(sacc[mg][nl][1], -2.f, q2a[mg] + k2v.y), 0.f);
                    float d2 = fmaxf(fmaf(sacc[mg][nl][2], -2.f, q2b[mg] + k2v.x), 0.f);
                    float d3 = fmaxf(fmaf(sacc[mg][nl][3], -2.f, q2b[mg] + k2v.y), 0.f);
                    sa[mg][u][0] = sqrt_approx(d0);
                    sa[mg][u][1] = sqrt_approx(d1);
                    sa[mg][u][2] = sqrt_approx(d2);
                    sa[mg][u][3] = sqrt_approx(d3);
                }
            }
            #pragma unroll
            for (int mg = 0; mg < 2; mg++) {
                uint32_t pa0 = h2ex2(pack_f16(sa[mg][0][0], sa[mg][0][1]) ^ 0x80008000u);
                uint32_t pa1 = h2ex2(pack_f16(sa[mg][0][2], sa[mg][0][3]) ^ 0x80008000u);
                uint32_t pa2 = h2ex2(pack_f16(sa[mg][1][0], sa[mg][1][1]) ^ 0x80008000u);
                uint32_t pa3 = h2ex2(pack_f16(sa[mg][1][2], sa[mg][1][3]) ^ 0x80008000u);
                // l partials from f16x2 pairs (rows g / g+8), folded to f32 immediately
                {
                    uint32_t la = hadd2u(pa0, pa2), lb = hadd2u(pa1, pa3);
                    float2 fa = __half22float2(*reinterpret_cast<__half2*>(&la));
                    float2 fb = __half22float2(*reinterpret_cast<__half2*>(&lb));
                    l0[mg] += fa.x + fa.y;
                    l1[mg] += fb.x + fb.y;
                }
                *(uint4*)(pMine + (mg * 4 + (2 * h + t)) * 128) =
                    make_uint4(pa0, pa1, pa2, pa3);
            }
        }
        __syncthreads();               // bar B: full P tile visible

        // ---- O += P V (per warp: 32 rows x 96 cols, cols 96h..+96) ----
        #pragma unroll
        for (int kg = 0; kg < 4; kg++) {
            uint4 pA0 = *(const uint4*)(sP + (((rb * 2 + 0) * 4 + kg) * 32 + lane) * 4);
            uint4 pA1 = *(const uint4*)(sP + (((rb * 2 + 1) * 4 + kg) * 32 + lane) * 4);
            const uint32_t* vp = sVB + buf * VB_SZ + (kg * 4 + t4) * LDVP + g * 48 + h * 24;
            #pragma unroll
            for (int jl = 0; jl < 6; jl++) {
                uint4 w = *(const uint4*)(vp + 4 * jl);
                mma16_f16(o[2*jl],      pA0.x, pA0.y, pA0.z, pA0.w, w.x, w.y);
                mma16_f16(o[2*jl+1],    pA0.x, pA0.y, pA0.z, pA0.w, w.z, w.w);
                mma16_f16(o[12+2*jl],   pA1.x, pA1.y, pA1.z, pA1.w, w.x, w.y);
                mma16_f16(o[12+2*jl+1], pA1.x, pA1.y, pA1.z, pA1.w, w.z, w.w);
            }
        }
    }

    // ---- epilogue: merge l key-halves across warp pair, normalize, write ----
    #pragma unroll
    for (int mg = 0; mg < 2; mg++) {
        l0[mg] += __shfl_xor_sync(0xffffffffu, l0[mg], 1);
        l0[mg] += __shfl_xor_sync(0xffffffffu, l0[mg], 2);
        l1[mg] += __shfl_xor_sync(0xffffffffu, l1[mg], 1);
        l1[mg] += __shfl_xor_sync(0xffffffffu, l1[mg], 2);
    }
    if (t4 == 0) {
        #pragma unroll
        for (int mg = 0; mg < 2; mg++) {
            sL[h * 128 + rb * 32 + mg * 16 + g]     = l0[mg];
            sL[h * 128 + rb * 32 + mg * 16 + g + 8] = l1[mg];
        }
    }
    __syncthreads();

    #pragma unroll
    for (int mg = 0; mg < 2; mg++) {
        int row = rb * 32 + mg * 16 + g;
        float il0 = 1.f / (sL[row]     + sL[128 + row]);
        float il1 = 1.f / (sL[row + 8] + sL[128 + row + 8]);
        size_t orow0 = ((size_t)(b * NTOK + q0 + row)) * DIMC + 96 * h;
        size_t orow1 = orow0 + (size_t)8 * DIMC;
        #pragma unroll
        for (int ntl = 0; ntl < 12; ntl++) {
            int col = ntl * 8 + 2 * t4;
            const float* oc = o[mg * 12 + ntl];
            *(float2*)(out + orow0 + col) = make_float2(oc[0] * il0, oc[1] * il0);
            *(float2*)(out + orow1 + col) = make_float2(oc[2] * il1, oc[3] * il1);
        }
    }
}

extern "C" void kernel_launch(void* const* d_in, const int* in_sizes, int n_in,
                              void* d_out, int out_size) {
    const float* qkv = (const float*)d_in[0];
    float* out = (float*)d_out;
    prepass_kernel<<<dim3(NTILES, NB), 256>>>(qkv);
    cudaFuncSetAttribute(qkv_l2attn_kernel,
                         cudaFuncAttributeMaxDynamicSharedMemorySize, SMEM_BYTES);
    dim3 grid(NTOK / BR, NB);
    qkv_l2attn_kernel<<<grid, NTHREADS, SMEM_BYTES>>>(qkv, out);
}